// round 5
// baseline (speedup 1.0000x reference)
#include <cuda_runtime.h>
#include <stdint.h>

#define NN 100000
#define NE 1000000
#define HDIM 128
#define NHEADS 4
#define NBLK 592              // 148 SMs x 4 co-resident blocks (guaranteed by launch_bounds)
#define NTHR 256
#define GSZ (NBLK * NTHR)     // 151552 threads

// ---------------- device scratch ----------------
__device__ float2        g_acc2[NN];       // per-dst {A,B}: acc = A - scalars[d]*B
__device__ double        g_loss;
__device__ int2          g_nrec[NN];       // {float_as_int(scalars[i]), node_code}
__device__ unsigned char g_ecodes[NE];
__device__ float         g_M[32][HDIM];    // rows 0-15: edge_emb@Wtop, 16-31: node_emb@Wbot
__device__ unsigned      g_bar_arrive = 0; // grid barrier arrivals
__device__ unsigned      g_bar_epoch  = 0; // grid barrier epoch (monotonic across replays)
__device__ unsigned      g_done = 0;       // finisher counter

__device__ __forceinline__ void red_add_f2(float2* addr, float a, float b) {
    asm volatile("red.global.add.v2.f32 [%0], {%1, %2};"
                 :: "l"(addr), "f"(a), "f"(b) : "memory");
}

// software grid barrier: all NBLK blocks must be co-resident
__device__ __forceinline__ void grid_barrier(unsigned target) {
    __syncthreads();
    if (threadIdx.x == 0) {
        __threadfence();
        unsigned old = atomicAdd(&g_bar_arrive, 1u);
        if (old == NBLK - 1u) {
            g_bar_arrive = 0;
            __threadfence();
            *(volatile unsigned*)&g_bar_epoch = target;     // release
        } else {
            while ((int)(*(volatile unsigned*)&g_bar_epoch - target) < 0) {}
            __threadfence();                                 // acquire
        }
    }
    __syncthreads();
}

__global__ void __launch_bounds__(NTHR, 4) fused_kernel(
    const int*   __restrict__ node_states,
    const int*   __restrict__ edge_states,
    const float* __restrict__ scalars,
    const int*   __restrict__ edge_index,
    const int*   __restrict__ brev,
    const float* __restrict__ target,
    const int*   __restrict__ training_step,
    const float* __restrict__ node_emb,
    const float* __restrict__ edge_emb,
    const float* __restrict__ combine_W,
    const float* __restrict__ combine_b,
    const float* __restrict__ keep_W,  const float* __restrict__ keep_b,
    const float* __restrict__ push_W,  const float* __restrict__ push_b,
    const float* __restrict__ pushn_W, const float* __restrict__ pushn_b,
    const float* __restrict__ inc_W,   const float* __restrict__ inc_b,
    float* __restrict__ out, int write_loss)
{
    __shared__ unsigned sh_e0;
    __shared__ float    sh_tmp[256];
    __shared__ float    sh_emb[HDIM];
    __shared__ float    shd[NHEADS][HDIM];
    __shared__ float    shT[NHEADS][32];   // [h][0..15]=TE, [h][16..31]=TN
    __shared__ float    shC[NHEADS];
    __shared__ float4   sP4[256];          // {p_inc, p_keep, p2+p3, p3}
    __shared__ float    warp_sums[8];
    __shared__ int      sh_last;

    int tid = threadIdx.x, bid = blockIdx.x;
    int gtid = bid * NTHR + tid;

    if (tid == 0) sh_e0 = *(volatile unsigned*)&g_bar_epoch;  // entry epoch
    __syncthreads();
    unsigned e0 = sh_e0;

    // ================= phase A: table matvec (blocks 0..31) + prep =================
    if (bid < 32) {
        int b = bid, k = b & 15, base = (b < 16) ? 0 : HDIM;
        const float* embrow = ((b < 16) ? edge_emb : node_emb) + k * HDIM;
        if (tid < HDIM) sh_emb[tid] = embrow[tid];
        __syncthreads();
        int j = tid & 127, h2 = tid >> 7;
        const float* Wp = combine_W + (base + h2 * 64) * HDIM + j;
        const float* ep = sh_emb + h2 * 64;
        float a = 0.f;
        #pragma unroll
        for (int i = 0; i < 64; i++) a = fmaf(ep[i], Wp[i * HDIM], a);
        sh_tmp[tid] = a;
        __syncthreads();
        if (tid < 128) g_M[b][tid] = sh_tmp[tid] + sh_tmp[tid + 128];
    }
    if (gtid < NN) {   // one shot: GSZ > NN
        int4 s = reinterpret_cast<const int4*>(node_states)[gtid];
        g_nrec[gtid] = make_int2(__float_as_int(scalars[gtid]),
                                 s.x + 2 * s.y + 4 * s.z + 8 * s.w);
        g_acc2[gtid] = make_float2(0.f, 0.f);
    }
    if (bid == 32 && tid == 0) g_loss = 0.0;
    for (int e = gtid; e < NE; e += GSZ) {   // coalesced per-lane stride
        int4 s = reinterpret_cast<const int4*>(edge_states)[e];
        g_ecodes[e] = (unsigned char)(s.x + 2 * s.y + 4 * s.z + 8 * s.w);
    }

    grid_barrier(e0 + 1);

    // ================= phase B prologue: per-block bake of sP4 =================
    {
        const float* Wh[NHEADS] = {inc_W, keep_W, push_W, pushn_W};
        const float* bh[NHEADS] = {inc_b, keep_b, push_b, pushn_b};
        if (tid < HDIM) {
            #pragma unroll
            for (int h = 0; h < NHEADS; h++)
                shd[h][tid] = Wh[h][2 * tid] - Wh[h][2 * tid + 1];
        }
        __syncthreads();
        int step = training_step[0];
        float tau = (step == -1) ? 0.1f
                  : (1.0f + (0.1f - 1.0f) * fminf((float)step / 10000.0f, 1.0f));
        float invtau = 1.0f / tau;
        {
            int outi = tid >> 1, half = tid & 1;   // 128 outputs, 2 threads each
            int h = outi >> 5, j = outi & 31;
            const float* dv = shd[h] + half * 64;
            const float* mr = &g_M[j][half * 64];  // L2-resident
            float t = 0.f;
            #pragma unroll
            for (int i = 0; i < 64; i++) t = fmaf(mr[i], dv[i], t);
            t += __shfl_xor_sync(0xFFFFFFFFu, t, 1);
            if (half == 0) shT[h][j] = t * invtau;
        }
        if (tid < NHEADS) {
            float c = 0.f;
            #pragma unroll 16
            for (int i = 0; i < HDIM; i++) c = fmaf(combine_b[i], shd[tid][i], c);
            shC[tid] = (c + bh[tid][0] - bh[tid][1]) * invtau;
        }
        __syncthreads();
        int ce = tid >> 4, cn = tid & 15;
        float p[NHEADS];
        #pragma unroll
        for (int h = 0; h < NHEADS; h++) {
            float logit = shT[h][ce] + shT[h][16 + cn] + shC[h];
            p[h] = 1.0f / (1.0f + __expf(-logit));
        }
        sP4[tid] = make_float4(p[0], p[1], p[2] + p[3], p[3]);
        __syncthreads();
    }

    // ================= phase B: edge pass =================
    float lsum = 0.f;
    for (int e = gtid; e < NE; e += GSZ) {
        int rev = brev[e];
        float s = scalars[e];
        unsigned ce = g_ecodes[rev];          // random byte gather (L2)
        int src, dst;
        if (e < NN) { src = e; dst = e; }     // dataset self-loop structure
        else { src = edge_index[e]; dst = edge_index[NE + e]; }
        int2 nr = g_nrec[src];                // random 8B gather (L2)
        float ssrc = __int_as_float(nr.x);
        float4 p = sP4[(ce << 4) | (unsigned)nr.y];
        red_add_f2(&g_acc2[dst], fmaf(p.z, s, p.w * ssrc), p.z);
        float ns = fmaf(s, p.y, p.x);         // increment + keep
        out[e] = ns;
        if (e >= NN) { float d = target[e] - ns; lsum = fmaf(d, d, lsum); }
    }

    grid_barrier(e0 + 2);

    // ================= phase C: node finalize + loss =================
    if (gtid < NN) {
        float2 a = g_acc2[gtid];
        float ns = out[gtid] + fmaf(-scalars[gtid], a.y, a.x);
        out[gtid] = ns;
        float d = target[gtid] - ns;
        lsum = fmaf(d, d, lsum);
    }
    #pragma unroll
    for (int o = 16; o > 0; o >>= 1) lsum += __shfl_down_sync(0xFFFFFFFFu, lsum, o);
    int lane = tid & 31, wid = tid >> 5;
    if (lane == 0) warp_sums[wid] = lsum;
    __syncthreads();
    if (wid == 0) {
        float v = (lane < 8) ? warp_sums[lane] : 0.f;
        #pragma unroll
        for (int o = 4; o > 0; o >>= 1) v += __shfl_down_sync(0xFFFFFFFFu, v, o);
        if (lane == 0) atomicAdd(&g_loss, (double)v);
    }
    if (tid == 0) {
        __threadfence();
        sh_last = (atomicAdd(&g_done, 1u) == NBLK - 1u);
    }
    __syncthreads();
    if (sh_last && tid == 0) {
        if (write_loss) out[NE] = (float)(g_loss / (double)NE);
        g_done = 0;   // reset for next replay
    }
}

// ---------------- launcher: ONE kernel ----------------
extern "C" void kernel_launch(void* const* d_in, const int* in_sizes, int n_in,
                              void* d_out, int out_size) {
    const int*   node_states = (const int*)  d_in[0];
    const int*   edge_states = (const int*)  d_in[1];
    const float* scalars     = (const float*)d_in[2];
    const int*   edge_index  = (const int*)  d_in[3];
    const int*   brev        = (const int*)  d_in[4];
    const float* batch_sc    = (const float*)d_in[5];
    const int*   train_step  = (const int*)  d_in[7];
    const float* node_emb    = (const float*)d_in[8];
    const float* edge_emb    = (const float*)d_in[9];
    const float* combine_W   = (const float*)d_in[10];
    const float* combine_b   = (const float*)d_in[11];
    const float* keep_W      = (const float*)d_in[12];
    const float* keep_b      = (const float*)d_in[13];
    const float* push_W      = (const float*)d_in[14];
    const float* push_b      = (const float*)d_in[15];
    const float* pushn_W     = (const float*)d_in[16];
    const float* pushn_b     = (const float*)d_in[17];
    const float* inc_W       = (const float*)d_in[18];
    const float* inc_b       = (const float*)d_in[19];

    fused_kernel<<<NBLK, NTHR>>>(
        node_states, edge_states, scalars, edge_index, brev, batch_sc,
        train_step, node_emb, edge_emb, combine_W, combine_b,
        keep_W, keep_b, push_W, push_b, pushn_W, pushn_b, inc_W, inc_b,
        (float*)d_out, out_size > NE ? 1 : 0);
}

// round 6
// speedup vs baseline: 1.0040x; 1.0040x over previous
#include <cuda_runtime.h>
#include <stdint.h>

#define NN 100000
#define NE 1000000
#define HDIM 128
#define NHEADS 4
#define NBLK 592              // 148 SMs x 4 co-resident blocks (guaranteed by launch_bounds)
#define NTHR 256
#define GSZ (NBLK * NTHR)     // 151552 threads

// ---------------- device scratch ----------------
__device__ float2        g_acc2[NN];       // per-dst {A,B}: acc = A - scalars[d]*B
__device__ double        g_loss;
__device__ int2          g_nrec[NN];       // {float_as_int(scalars[i]), node_code}
__device__ unsigned char g_ecodes[NE];
__device__ float         g_M[32][HDIM];    // rows 0-15: edge_emb@Wtop, 16-31: node_emb@Wbot
__device__ unsigned      g_bar_arrive = 0; // grid barrier arrivals
__device__ unsigned      g_bar_epoch  = 0; // grid barrier epoch (monotonic across replays)
__device__ unsigned      g_done = 0;       // finisher counter

__device__ __forceinline__ void red_add_f2(float2* addr, float a, float b) {
    asm volatile("red.global.add.v2.f32 [%0], {%1, %2};"
                 :: "l"(addr), "f"(a), "f"(b) : "memory");
}

// software grid barrier: all NBLK blocks must be co-resident
__device__ __forceinline__ void grid_barrier(unsigned target) {
    __syncthreads();
    if (threadIdx.x == 0) {
        __threadfence();
        unsigned old = atomicAdd(&g_bar_arrive, 1u);
        if (old == NBLK - 1u) {
            g_bar_arrive = 0;
            __threadfence();
            *(volatile unsigned*)&g_bar_epoch = target;     // release
        } else {
            while ((int)(*(volatile unsigned*)&g_bar_epoch - target) < 0) {}
            __threadfence();                                 // acquire
        }
    }
    __syncthreads();
}

__global__ void __launch_bounds__(NTHR, 4) fused_kernel(
    const int*   __restrict__ node_states,
    const int*   __restrict__ edge_states,
    const float* __restrict__ scalars,
    const int*   __restrict__ edge_index,
    const int*   __restrict__ brev,
    const float* __restrict__ target,
    const int*   __restrict__ training_step,
    const float* __restrict__ node_emb,
    const float* __restrict__ edge_emb,
    const float* __restrict__ combine_W,
    const float* __restrict__ combine_b,
    const float* __restrict__ keep_W,  const float* __restrict__ keep_b,
    const float* __restrict__ push_W,  const float* __restrict__ push_b,
    const float* __restrict__ pushn_W, const float* __restrict__ pushn_b,
    const float* __restrict__ inc_W,   const float* __restrict__ inc_b,
    float* __restrict__ out, int write_loss)
{
    __shared__ unsigned sh_e0;
    __shared__ float    sh_tmp[256];
    __shared__ float    sh_emb[HDIM];
    __shared__ float    shd[NHEADS][HDIM];
    __shared__ float    shT[NHEADS][32];   // [h][0..15]=TE, [h][16..31]=TN
    __shared__ float    shC[NHEADS];
    __shared__ float4   sP4[256];          // {p_inc, p_keep, p2+p3, p3}
    __shared__ float    warp_sums[8];
    __shared__ int      sh_last;

    int tid = threadIdx.x, bid = blockIdx.x;
    int gtid = bid * NTHR + tid;

    if (tid == 0) sh_e0 = *(volatile unsigned*)&g_bar_epoch;  // entry epoch
    __syncthreads();
    unsigned e0 = sh_e0;

    // ================= phase A: table matvec (blocks 0..31) + prep =================
    if (bid < 32) {
        int b = bid, k = b & 15, base = (b < 16) ? 0 : HDIM;
        const float* embrow = ((b < 16) ? edge_emb : node_emb) + k * HDIM;
        if (tid < HDIM) sh_emb[tid] = embrow[tid];
        __syncthreads();
        int j = tid & 127, h2 = tid >> 7;
        const float* Wp = combine_W + (base + h2 * 64) * HDIM + j;
        const float* ep = sh_emb + h2 * 64;
        float a = 0.f;
        #pragma unroll
        for (int i = 0; i < 64; i++) a = fmaf(ep[i], Wp[i * HDIM], a);
        sh_tmp[tid] = a;
        __syncthreads();
        if (tid < 128) g_M[b][tid] = sh_tmp[tid] + sh_tmp[tid + 128];
    }
    if (gtid < NN) {   // one shot: GSZ > NN
        int4 s = reinterpret_cast<const int4*>(node_states)[gtid];
        g_nrec[gtid] = make_int2(__float_as_int(scalars[gtid]),
                                 s.x + 2 * s.y + 4 * s.z + 8 * s.w);
        g_acc2[gtid] = make_float2(0.f, 0.f);
    }
    if (bid == 32 && tid == 0) g_loss = 0.0;
    for (int e = gtid; e < NE; e += GSZ) {   // coalesced per-lane stride
        int4 s = reinterpret_cast<const int4*>(edge_states)[e];
        g_ecodes[e] = (unsigned char)(s.x + 2 * s.y + 4 * s.z + 8 * s.w);
    }

    grid_barrier(e0 + 1);

    // ================= phase B prologue: per-block bake of sP4 =================
    {
        const float* Wh[NHEADS] = {inc_W, keep_W, push_W, pushn_W};
        const float* bh[NHEADS] = {inc_b, keep_b, push_b, pushn_b};
        if (tid < HDIM) {
            #pragma unroll
            for (int h = 0; h < NHEADS; h++)
                shd[h][tid] = Wh[h][2 * tid] - Wh[h][2 * tid + 1];
        }
        __syncthreads();
        int step = training_step[0];
        float tau = (step == -1) ? 0.1f
                  : (1.0f + (0.1f - 1.0f) * fminf((float)step / 10000.0f, 1.0f));
        float invtau = 1.0f / tau;
        {
            int outi = tid >> 1, half = tid & 1;   // 128 outputs, 2 threads each
            int h = outi >> 5, j = outi & 31;
            const float* dv = shd[h] + half * 64;
            const float* mr = &g_M[j][half * 64];  // L2-resident
            float t = 0.f;
            #pragma unroll
            for (int i = 0; i < 64; i++) t = fmaf(mr[i], dv[i], t);
            t += __shfl_xor_sync(0xFFFFFFFFu, t, 1);
            if (half == 0) shT[h][j] = t * invtau;
        }
        if (tid < NHEADS) {
            float c = 0.f;
            #pragma unroll 16
            for (int i = 0; i < HDIM; i++) c = fmaf(combine_b[i], shd[tid][i], c);
            shC[tid] = (c + bh[tid][0] - bh[tid][1]) * invtau;
        }
        __syncthreads();
        int ce = tid >> 4, cn = tid & 15;
        float p[NHEADS];
        #pragma unroll
        for (int h = 0; h < NHEADS; h++) {
            float logit = shT[h][ce] + shT[h][16 + cn] + shC[h];
            p[h] = 1.0f / (1.0f + __expf(-logit));
        }
        sP4[tid] = make_float4(p[0], p[1], p[2] + p[3], p[3]);
        __syncthreads();
    }

    // ================= phase B: edge pass =================
    float lsum = 0.f;
    for (int e = gtid; e < NE; e += GSZ) {
        int rev = brev[e];
        float s = scalars[e];
        unsigned ce = g_ecodes[rev];          // random byte gather (L2)
        int src, dst;
        if (e < NN) { src = e; dst = e; }     // dataset self-loop structure
        else { src = edge_index[e]; dst = edge_index[NE + e]; }
        int2 nr = g_nrec[src];                // random 8B gather (L2)
        float ssrc = __int_as_float(nr.x);
        float4 p = sP4[(ce << 4) | (unsigned)nr.y];
        red_add_f2(&g_acc2[dst], fmaf(p.z, s, p.w * ssrc), p.z);
        float ns = fmaf(s, p.y, p.x);         // increment + keep
        out[e] = ns;
        if (e >= NN) { float d = target[e] - ns; lsum = fmaf(d, d, lsum); }
    }

    grid_barrier(e0 + 2);

    // ================= phase C: node finalize + loss =================
    if (gtid < NN) {
        float2 a = g_acc2[gtid];
        float ns = out[gtid] + fmaf(-scalars[gtid], a.y, a.x);
        out[gtid] = ns;
        float d = target[gtid] - ns;
        lsum = fmaf(d, d, lsum);
    }
    #pragma unroll
    for (int o = 16; o > 0; o >>= 1) lsum += __shfl_down_sync(0xFFFFFFFFu, lsum, o);
    int lane = tid & 31, wid = tid >> 5;
    if (lane == 0) warp_sums[wid] = lsum;
    __syncthreads();
    if (wid == 0) {
        float v = (lane < 8) ? warp_sums[lane] : 0.f;
        #pragma unroll
        for (int o = 4; o > 0; o >>= 1) v += __shfl_down_sync(0xFFFFFFFFu, v, o);
        if (lane == 0) atomicAdd(&g_loss, (double)v);
    }
    if (tid == 0) {
        __threadfence();
        sh_last = (atomicAdd(&g_done, 1u) == NBLK - 1u);
    }
    __syncthreads();
    if (sh_last && tid == 0) {
        if (write_loss) out[NE] = (float)(g_loss / (double)NE);
        g_done = 0;   // reset for next replay
    }
}

// ---------------- launcher: ONE kernel ----------------
extern "C" void kernel_launch(void* const* d_in, const int* in_sizes, int n_in,
                              void* d_out, int out_size) {
    const int*   node_states = (const int*)  d_in[0];
    const int*   edge_states = (const int*)  d_in[1];
    const float* scalars     = (const float*)d_in[2];
    const int*   edge_index  = (const int*)  d_in[3];
    const int*   brev        = (const int*)  d_in[4];
    const float* batch_sc    = (const float*)d_in[5];
    const int*   train_step  = (const int*)  d_in[7];
    const float* node_emb    = (const float*)d_in[8];
    const float* edge_emb    = (const float*)d_in[9];
    const float* combine_W   = (const float*)d_in[10];
    const float* combine_b   = (const float*)d_in[11];
    const float* keep_W      = (const float*)d_in[12];
    const float* keep_b      = (const float*)d_in[13];
    const float* push_W      = (const float*)d_in[14];
    const float* push_b      = (const float*)d_in[15];
    const float* pushn_W     = (const float*)d_in[16];
    const float* pushn_b     = (const float*)d_in[17];
    const float* inc_W       = (const float*)d_in[18];
    const float* inc_b       = (const float*)d_in[19];

    fused_kernel<<<NBLK, NTHR>>>(
        node_states, edge_states, scalars, edge_index, brev, batch_sc,
        train_step, node_emb, edge_emb, combine_W, combine_b,
        keep_W, keep_b, push_W, push_b, pushn_W, pushn_b, inc_W, inc_b,
        (float*)d_out, out_size > NE ? 1 : 0);
}

// round 7
// speedup vs baseline: 1.3439x; 1.3385x over previous
#include <cuda_runtime.h>
#include <stdint.h>

#define NN 100000
#define NE 1000000
#define HDIM 128
#define NHEADS 4
#define NTBLK 32   // table-builder blocks prefixed onto node-prep grid

// ---------------- device scratch ----------------
__device__ float2        g_acc2[NN];       // per-dst {A,B}: acc = A - scalars[d]*B
__device__ double        g_loss;
__device__ int2          g_nrec[NN];       // {float_as_int(scalars[i]), node_code}
__device__ float         g_M[32][HDIM];    // rows 0-15: edge_emb@Wtop, 16-31: node_emb@Wbot
__device__ float4        g_P4[256];        // {p_inc, p_keep, p2+p3, p3} per (ce<<4)|cn
__device__ unsigned      g_cnt1 = 0;       // table completion counter
__device__ unsigned      g_done = 0;       // pass2 completion counter

__device__ __forceinline__ void red_add_f2(float2* addr, float a, float b) {
    asm volatile("red.global.add.v2.f32 [%0], {%1, %2};"
                 :: "l"(addr), "f"(a), "f"(b) : "memory");
}

// ---------------- kernel A: tables (blocks 0..31) + node prep (rest) ----------------
__global__ void __launch_bounds__(256) prep_tables_kernel(
        const int*   __restrict__ node_states,
        const float* __restrict__ scalars,
        const float* __restrict__ combine_W,   // (256,128)
        const float* __restrict__ combine_b,   // (128,)
        const float* __restrict__ node_emb,    // (16,128)
        const float* __restrict__ edge_emb,    // (16,128)
        const float* __restrict__ keep_W,  const float* __restrict__ keep_b,
        const float* __restrict__ push_W,  const float* __restrict__ push_b,
        const float* __restrict__ pushn_W, const float* __restrict__ pushn_b,
        const float* __restrict__ inc_W,   const float* __restrict__ inc_b,
        const int*   __restrict__ training_step) {
    int tid = threadIdx.x;
    int blk = blockIdx.x;

    if (blk >= NTBLK) {
        // node prep: one node per thread (coalesced)
        int i = (blk - NTBLK) * 256 + tid;
        if (i < NN) {
            int4 s = reinterpret_cast<const int4*>(node_states)[i];
            g_nrec[i] = make_int2(__float_as_int(scalars[i]),
                                  s.x + 2 * s.y + 4 * s.z + 8 * s.w);
            g_acc2[i] = make_float2(0.f, 0.f);
        }
        if (i == 0) g_loss = 0.0;
        return;
    }

    // ---------------- table part ----------------
    __shared__ float sh_emb[HDIM];
    __shared__ float sh_part[256];
    __shared__ float shM[32][HDIM + 1];
    __shared__ float shd[NHEADS][HDIM];
    __shared__ float shT[NHEADS][32];   // [h][0..15]=TE, [h][16..31]=TN
    __shared__ float shC[NHEADS];
    __shared__ int   sh_last;

    int b = blk, k = b & 15;
    int base = (b < 16) ? 0 : HDIM;
    const float* embrow = ((b < 16) ? edge_emb : node_emb) + k * HDIM;

    if (tid < HDIM) sh_emb[tid] = embrow[tid];
    __syncthreads();

    {   // M[b][j] = sum_i emb[i]*W[base+i][j]; i split in 2 halves across threads
        int j = tid & 127, h2 = tid >> 7;
        const float* Wp = combine_W + (base + h2 * 64) * HDIM + j;
        const float* ep = sh_emb + h2 * 64;
        float a = 0.f;
        #pragma unroll
        for (int i = 0; i < 64; i++) a = fmaf(ep[i], Wp[i * HDIM], a);
        sh_part[tid] = a;
    }
    __syncthreads();
    if (tid < 128) g_M[b][tid] = sh_part[tid] + sh_part[tid + 128];

    __threadfence();
    __syncthreads();
    if (tid == 0) sh_last = (atomicAdd(&g_cnt1, 1u) == NTBLK - 1u);
    __syncthreads();
    if (!sh_last) return;

    // -------- finisher: bake g_P4 --------
    for (int t = tid; t < 32 * HDIM; t += 256)
        shM[t >> 7][t & 127] = g_M[t >> 7][t & 127];

    const float* Wh[NHEADS] = {inc_W, keep_W, push_W, pushn_W};
    const float* bh[NHEADS] = {inc_b, keep_b, push_b, pushn_b};
    if (tid < HDIM) {
        #pragma unroll
        for (int h = 0; h < NHEADS; h++)
            shd[h][tid] = Wh[h][2 * tid] - Wh[h][2 * tid + 1];
    }
    __syncthreads();

    int step = training_step[0];
    float tau = (step == -1) ? 0.1f
              : (1.0f + (0.1f - 1.0f) * fminf((float)step / 10000.0f, 1.0f));
    float invtau = 1.0f / tau;

    {   // 128 outputs, 2 threads each
        int outi = tid >> 1, half = tid & 1;
        int h = outi >> 5, j = outi & 31;
        const float* dv = shd[h] + half * 64;
        const float* mr = &shM[j][half * 64];
        float t = 0.f;
        #pragma unroll
        for (int i = 0; i < 64; i++) t = fmaf(mr[i], dv[i], t);
        t += __shfl_xor_sync(0xFFFFFFFFu, t, 1);
        if (half == 0) shT[h][j] = t * invtau;
    }
    if (tid < NHEADS) {
        float c = 0.f;
        #pragma unroll 16
        for (int i = 0; i < HDIM; i++) c = fmaf(combine_b[i], shd[tid][i], c);
        shC[tid] = (c + bh[tid][0] - bh[tid][1]) * invtau;
    }
    __syncthreads();

    {   // 256-entry float4 table
        int ce = tid >> 4, cn = tid & 15;
        float p[NHEADS];
        #pragma unroll
        for (int h = 0; h < NHEADS; h++) {
            float logit = shT[h][ce] + shT[h][16 + cn] + shC[h];
            p[h] = 1.0f / (1.0f + __expf(-logit));
        }
        g_P4[tid] = make_float4(p[0], p[1], p[2] + p[3], p[3]);
    }
    if (tid == 0) g_cnt1 = 0;   // reset for next graph replay
}

// ---------------- kernel B: main edge pass (gathers edge_states directly) ----------------
__global__ void __launch_bounds__(256) pass1_kernel(const int* __restrict__ edge_states,
                                                    const int* __restrict__ edge_index,
                                                    const int* __restrict__ brev,
                                                    const float* __restrict__ scalars,
                                                    const float* __restrict__ target,
                                                    float* __restrict__ out) {
    __shared__ float4 sP4[256];
    __shared__ float warp_sums[8];
    int tid = threadIdx.x;
    sP4[tid] = g_P4[tid];
    __syncthreads();

    int e = blockIdx.x * blockDim.x + tid;
    float sq = 0.0f;
    if (e < NE) {
        int rev = brev[e];
        float s = scalars[e];

        // random 16B gather — same 32B-sector cost as a byte gather, no prep stream
        int4 est = reinterpret_cast<const int4*>(edge_states)[rev];
        unsigned ce = (unsigned)(est.x + 2 * est.y + 4 * est.z + 8 * est.w);

        int src, dst;
        if (e < NN) { src = e; dst = e; }     // dataset self-loop structure
        else { src = edge_index[e]; dst = edge_index[NE + e]; }

        int2 nr = g_nrec[src];                // random 8B gather
        float ssrc = __int_as_float(nr.x);
        float4 p = sP4[(ce << 4) | (unsigned)nr.y];   // {inc, keep, pw, p3}

        red_add_f2(&g_acc2[dst], fmaf(p.z, s, p.w * ssrc), p.z);

        float ns = fmaf(s, p.y, p.x);         // increment + keep
        out[e] = ns;
        if (e >= NN) {                        // edge_push==0 -> final; loss here
            float d = target[e] - ns;
            sq = d * d;
        }
    }

    #pragma unroll
    for (int o = 16; o > 0; o >>= 1) sq += __shfl_down_sync(0xFFFFFFFFu, sq, o);
    int lane = tid & 31, wid = tid >> 5;
    if (lane == 0) warp_sums[wid] = sq;
    __syncthreads();
    if (wid == 0) {
        float v = (lane < 8) ? warp_sums[lane] : 0.0f;
        #pragma unroll
        for (int o = 4; o > 0; o >>= 1) v += __shfl_down_sync(0xFFFFFFFFu, v, o);
        if (lane == 0 && v != 0.0f) atomicAdd(&g_loss, (double)v);
    }
}

// ---------------- kernel C: finalize first N + loss (4 elems/thread) ----------------
__global__ void __launch_bounds__(256) pass2_kernel(const float* __restrict__ scalars,
                                                    const float* __restrict__ target,
                                                    float* __restrict__ out,
                                                    int write_loss) {
    __shared__ float warp_sums[8];
    __shared__ int sh_last;
    int tid = threadIdx.x;
    int q = (blockIdx.x * blockDim.x + tid) * 4;   // first node of quad

    float sq = 0.0f;
    if (q < NN) {                                  // NN % 4 == 0
        int p = q >> 1;
        float4 a01 = reinterpret_cast<const float4*>(g_acc2)[p];      // {A0,B0,A1,B1}
        float4 a23 = reinterpret_cast<const float4*>(g_acc2)[p + 1];
        float4 o  = *reinterpret_cast<const float4*>(out + q);
        float4 sc = *reinterpret_cast<const float4*>(scalars + q);
        float4 tg = *reinterpret_cast<const float4*>(target + q);
        float ns0 = o.x + fmaf(-sc.x, a01.y, a01.x);
        float ns1 = o.y + fmaf(-sc.y, a01.w, a01.z);
        float ns2 = o.z + fmaf(-sc.z, a23.y, a23.x);
        float ns3 = o.w + fmaf(-sc.w, a23.w, a23.z);
        *reinterpret_cast<float4*>(out + q) = make_float4(ns0, ns1, ns2, ns3);
        float d0 = tg.x - ns0, d1 = tg.y - ns1, d2 = tg.z - ns2, d3 = tg.w - ns3;
        sq = fmaf(d0, d0, fmaf(d1, d1, fmaf(d2, d2, d3 * d3)));
    }

    #pragma unroll
    for (int o = 16; o > 0; o >>= 1) sq += __shfl_down_sync(0xFFFFFFFFu, sq, o);
    int lane = tid & 31, wid = tid >> 5;
    if (lane == 0) warp_sums[wid] = sq;
    __syncthreads();
    if (wid == 0) {
        float v = (lane < 8) ? warp_sums[lane] : 0.0f;
        #pragma unroll
        for (int o = 4; o > 0; o >>= 1) v += __shfl_down_sync(0xFFFFFFFFu, v, o);
        if (lane == 0) atomicAdd(&g_loss, (double)v);
    }

    if (tid == 0) {
        __threadfence();
        sh_last = (atomicAdd(&g_done, 1u) == gridDim.x - 1);
    }
    __syncthreads();
    if (sh_last && tid == 0) {
        if (write_loss) out[NE] = (float)(g_loss / (double)NE);
        g_done = 0;   // reset for next replay
    }
}

// ---------------- launcher ----------------
extern "C" void kernel_launch(void* const* d_in, const int* in_sizes, int n_in,
                              void* d_out, int out_size) {
    const int*   node_states = (const int*)  d_in[0];
    const int*   edge_states = (const int*)  d_in[1];
    const float* scalars     = (const float*)d_in[2];
    const int*   edge_index  = (const int*)  d_in[3];
    const int*   brev        = (const int*)  d_in[4];
    const float* batch_sc    = (const float*)d_in[5];
    const int*   train_step  = (const int*)  d_in[7];
    const float* node_emb    = (const float*)d_in[8];
    const float* edge_emb    = (const float*)d_in[9];
    const float* combine_W   = (const float*)d_in[10];
    const float* combine_b   = (const float*)d_in[11];
    const float* keep_W      = (const float*)d_in[12];
    const float* keep_b      = (const float*)d_in[13];
    const float* push_W      = (const float*)d_in[14];
    const float* push_b      = (const float*)d_in[15];
    const float* pushn_W     = (const float*)d_in[16];
    const float* pushn_b     = (const float*)d_in[17];
    const float* inc_W       = (const float*)d_in[18];
    const float* inc_b       = (const float*)d_in[19];

    float* out = (float*)d_out;

    int node_blocks = (NN + 255) / 256;            // 391
    prep_tables_kernel<<<node_blocks + NTBLK, 256>>>(
        node_states, scalars, combine_W, combine_b, node_emb, edge_emb,
        keep_W, keep_b, push_W, push_b, pushn_W, pushn_b, inc_W, inc_b,
        train_step);
    pass1_kernel<<<(NE + 255) / 256, 256>>>(edge_states, edge_index, brev,
                                            scalars, batch_sc, out);
    pass2_kernel<<<(NN / 4 + 255) / 256, 256>>>(scalars, batch_sc, out,
                                                out_size > NE ? 1 : 0);
}

// round 8
// speedup vs baseline: 2.2144x; 1.6478x over previous
#include <cuda_runtime.h>
#include <stdint.h>

#define NN 100000
#define NE 1000000
#define HDIM 128
#define NHEADS 4
#define NTBLK 32   // table-builder blocks prefixed onto prep grid

// ---------------- device scratch ----------------
__device__ float2        g_acc2[NN];        // per-dst {A,B}: acc = A - scalars[d]*B
__device__ double        g_loss;
__device__ int2          g_nrec[NN];        // {float_as_int(scalars[i]), node_code}
__device__ unsigned char g_ecodes[NE];
__device__ float         g_T[NHEADS][32];   // raw head dots: [h][0..15]=TE, [h][16..31]=TN
__device__ float4        g_P4[256];         // {p_inc, p_keep, p2+p3, p3} per (ce<<4)|cn
__device__ unsigned      g_cnt1 = 0;        // table completion counter
__device__ unsigned      g_done = 0;        // pass2 completion counter

__device__ __forceinline__ void red_add_f2(float2* addr, float a, float b) {
    asm volatile("red.global.add.v2.f32 [%0], {%1, %2};"
                 :: "l"(addr), "f"(a), "f"(b) : "memory");
}

// ---------------- kernel A: tables (blocks 0..31, shared-staged) + prep (rest) ----------------
__global__ void __launch_bounds__(256) prep_tables_kernel(
        const int*   __restrict__ node_states,
        const int*   __restrict__ edge_states,
        const float* __restrict__ scalars,
        const float* __restrict__ combine_W,   // (256,128)
        const float* __restrict__ combine_b,   // (128,)
        const float* __restrict__ node_emb,    // (16,128)
        const float* __restrict__ edge_emb,    // (16,128)
        const float* __restrict__ keep_W,  const float* __restrict__ keep_b,
        const float* __restrict__ push_W,  const float* __restrict__ push_b,
        const float* __restrict__ pushn_W, const float* __restrict__ pushn_b,
        const float* __restrict__ inc_W,   const float* __restrict__ inc_b,
        const int*   __restrict__ training_step) {
    int tid = threadIdx.x;
    int blk = blockIdx.x;

    if (blk >= NTBLK) {
        // ---------------- prep part: 1 edge + 1 node per thread (coalesced) ----------------
        int i = (blk - NTBLK) * 256 + tid;
        if (i < NE) {
            int4 s = __ldcs(reinterpret_cast<const int4*>(edge_states) + i);
            g_ecodes[i] = (unsigned char)(s.x + 2 * s.y + 4 * s.z + 8 * s.w);
        }
        if (i < NN) {
            int4 s = reinterpret_cast<const int4*>(node_states)[i];
            g_nrec[i] = make_int2(__float_as_int(scalars[i]),
                                  s.x + 2 * s.y + 4 * s.z + 8 * s.w);
            g_acc2[i] = make_float2(0.f, 0.f);
        }
        if (i == 0) g_loss = 0.0;
        return;
    }

    // ---------------- table block b: M[b][:] = emb_row_b @ W_half, then 4 head dots ----------------
    __shared__ float sW[64 * HDIM];      // 32KB staging (2 stages of 64 rows)
    __shared__ float sEmb[HDIM];
    __shared__ float sD[NHEADS][HDIM];   // per-head direction vectors
    __shared__ float sPart[256];
    __shared__ float sRed[NHEADS][4];    // per-warp partials for head dots
    __shared__ int   sh_last;

    int b = blk, k = b & 15;
    int base = (b < 16) ? 0 : HDIM;
    const float* embrow = ((b < 16) ? edge_emb : node_emb) + k * HDIM;

    if (tid < HDIM) sEmb[tid] = embrow[tid];
    {   // load 4 head direction vectors (512 elems, 2 per thread)
        const float* Wh[NHEADS] = {inc_W, keep_W, push_W, pushn_W};
        #pragma unroll
        for (int t = tid; t < NHEADS * HDIM; t += 256) {
            int h = t >> 7, i = t & 127;
            sD[h][i] = Wh[h][2 * i] - Wh[h][2 * i + 1];
        }
    }
    __syncthreads();

    int j = tid & 127, half = tid >> 7;
    float acc = 0.f;
    #pragma unroll
    for (int stage = 0; stage < 2; stage++) {
        // cooperative coalesced load of 64 rows (32KB) via float4: 8 per thread
        const float4* Wv = reinterpret_cast<const float4*>(combine_W + (base + stage * 64) * HDIM);
        float4* sWv = reinterpret_cast<float4*>(sW);
        #pragma unroll
        for (int t = 0; t < 8; t++)
            sWv[t * 256 + tid] = Wv[t * 256 + tid];
        __syncthreads();
        // thread (j,half) accumulates its 32 i-terms of this stage
        const float* eb = sEmb + stage * 64 + half * 32;
        const float* ws = sW + (half * 32) * HDIM + j;
        #pragma unroll
        for (int i = 0; i < 32; i++)
            acc = fmaf(eb[i], ws[i * HDIM], acc);
        __syncthreads();
    }
    sPart[tid] = acc;
    __syncthreads();

    // threads 0..127 own M[b][j]; compute 4 head dots via shuffle trees
    float m = 0.f;
    if (tid < 128) {
        m = sPart[tid] + sPart[tid + 128];
        float v0 = m * sD[0][tid], v1 = m * sD[1][tid];
        float v2 = m * sD[2][tid], v3 = m * sD[3][tid];
        #pragma unroll
        for (int o = 16; o > 0; o >>= 1) {
            v0 += __shfl_down_sync(0xFFFFFFFFu, v0, o);
            v1 += __shfl_down_sync(0xFFFFFFFFu, v1, o);
            v2 += __shfl_down_sync(0xFFFFFFFFu, v2, o);
            v3 += __shfl_down_sync(0xFFFFFFFFu, v3, o);
        }
        int w = tid >> 5;
        if ((tid & 31) == 0) {
            sRed[0][w] = v0; sRed[1][w] = v1; sRed[2][w] = v2; sRed[3][w] = v3;
        }
    }
    __syncthreads();
    if (tid < NHEADS)
        g_T[tid][b] = sRed[tid][0] + sRed[tid][1] + sRed[tid][2] + sRed[tid][3];

    __threadfence();
    __syncthreads();
    if (tid == 0) sh_last = (atomicAdd(&g_cnt1, 1u) == NTBLK - 1u);
    __syncthreads();
    if (!sh_last) return;

    // -------- finisher: constants + bake g_P4 --------
    __shared__ float sC[NHEADS];
    __shared__ float sT[NHEADS][32];
    const float* bh[NHEADS] = {inc_b, keep_b, push_b, pushn_b};
    if (tid < 128) {   // head constants: dot(combine_b, d_h), 1 warp per head
        int h = tid >> 5, l = tid & 31;
        float c = combine_b[l] * sD[h][l]
                + combine_b[l + 32] * sD[h][l + 32]
                + combine_b[l + 64] * sD[h][l + 64]
                + combine_b[l + 96] * sD[h][l + 96];
        #pragma unroll
        for (int o = 16; o > 0; o >>= 1) c += __shfl_down_sync(0xFFFFFFFFu, c, o);
        if (l == 0) sC[h] = c + bh[h][0] - bh[h][1];
    }
    if (tid < NHEADS * 32) sT[tid >> 5][tid & 31] = g_T[tid >> 5][tid & 31];
    __syncthreads();

    int step = training_step[0];
    float tau = (step == -1) ? 0.1f
              : (1.0f + (0.1f - 1.0f) * fminf((float)step / 10000.0f, 1.0f));
    float invtau = 1.0f / tau;

    {   // bake 256-entry float4 table
        int ce = tid >> 4, cn = tid & 15;
        float p[NHEADS];
        #pragma unroll
        for (int h = 0; h < NHEADS; h++) {
            float logit = (sT[h][ce] + sT[h][16 + cn] + sC[h]) * invtau;
            p[h] = 1.0f / (1.0f + __expf(-logit));
        }
        g_P4[tid] = make_float4(p[0], p[1], p[2] + p[3], p[3]);
    }
    if (tid == 0) g_cnt1 = 0;   // reset for next graph replay
}

// ---------------- kernel B: main edge pass, 2 edges/thread ----------------
__global__ void __launch_bounds__(256) pass1_kernel(const int* __restrict__ edge_index,
                                                    const int* __restrict__ brev,
                                                    const float* __restrict__ scalars,
                                                    const float* __restrict__ target,
                                                    float* __restrict__ out) {
    __shared__ float4 sP4[256];
    __shared__ float warp_sums[8];
    int tid = threadIdx.x;
    sP4[tid] = g_P4[tid];
    __syncthreads();

    int e0 = blockIdx.x * 512 + tid;
    int e1 = e0 + 256;
    float sq = 0.0f;

    // front-batch independent loads for both edges
    int rev0 = 0, rev1 = 0;  float s0 = 0.f, s1 = 0.f;
    int src0 = 0, dst0 = 0, src1 = 0, dst1 = 0;
    bool v0 = (e0 < NE), v1 = (e1 < NE);
    if (v0) {
        rev0 = brev[e0]; s0 = scalars[e0];
        if (e0 < NN) { src0 = e0; dst0 = e0; }
        else { src0 = edge_index[e0]; dst0 = edge_index[NE + e0]; }
    }
    if (v1) {
        rev1 = brev[e1]; s1 = scalars[e1];
        if (e1 < NN) { src1 = e1; dst1 = e1; }
        else { src1 = edge_index[e1]; dst1 = edge_index[NE + e1]; }
    }
    unsigned ce0 = 0, ce1 = 0;
    if (v0) ce0 = g_ecodes[rev0];
    if (v1) ce1 = g_ecodes[rev1];
    int2 nr0 = make_int2(0, 0), nr1 = make_int2(0, 0);
    if (v0) nr0 = g_nrec[src0];
    if (v1) nr1 = g_nrec[src1];

    if (v0) {
        float ssrc = __int_as_float(nr0.x);
        float4 p = sP4[(ce0 << 4) | (unsigned)nr0.y];
        red_add_f2(&g_acc2[dst0], fmaf(p.z, s0, p.w * ssrc), p.z);
        float ns = fmaf(s0, p.y, p.x);
        out[e0] = ns;
        if (e0 >= NN) { float d = target[e0] - ns; sq = fmaf(d, d, sq); }
    }
    if (v1) {
        float ssrc = __int_as_float(nr1.x);
        float4 p = sP4[(ce1 << 4) | (unsigned)nr1.y];
        red_add_f2(&g_acc2[dst1], fmaf(p.z, s1, p.w * ssrc), p.z);
        float ns = fmaf(s1, p.y, p.x);
        out[e1] = ns;
        if (e1 >= NN) { float d = target[e1] - ns; sq = fmaf(d, d, sq); }
    }

    #pragma unroll
    for (int o = 16; o > 0; o >>= 1) sq += __shfl_down_sync(0xFFFFFFFFu, sq, o);
    int lane = tid & 31, wid = tid >> 5;
    if (lane == 0) warp_sums[wid] = sq;
    __syncthreads();
    if (wid == 0) {
        float v = (lane < 8) ? warp_sums[lane] : 0.0f;
        #pragma unroll
        for (int o = 4; o > 0; o >>= 1) v += __shfl_down_sync(0xFFFFFFFFu, v, o);
        if (lane == 0 && v != 0.0f) atomicAdd(&g_loss, (double)v);
    }
}

// ---------------- kernel C: finalize first N + loss (4 elems/thread) ----------------
__global__ void __launch_bounds__(256) pass2_kernel(const float* __restrict__ scalars,
                                                    const float* __restrict__ target,
                                                    float* __restrict__ out,
                                                    int write_loss) {
    __shared__ float warp_sums[8];
    __shared__ int sh_last;
    int tid = threadIdx.x;
    int q = (blockIdx.x * blockDim.x + tid) * 4;

    float sq = 0.0f;
    if (q < NN) {                                  // NN % 4 == 0
        int p = q >> 1;
        float4 a01 = reinterpret_cast<const float4*>(g_acc2)[p];
        float4 a23 = reinterpret_cast<const float4*>(g_acc2)[p + 1];
        float4 o  = *reinterpret_cast<const float4*>(out + q);
        float4 sc = *reinterpret_cast<const float4*>(scalars + q);
        float4 tg = *reinterpret_cast<const float4*>(target + q);
        float ns0 = o.x + fmaf(-sc.x, a01.y, a01.x);
        float ns1 = o.y + fmaf(-sc.y, a01.w, a01.z);
        float ns2 = o.z + fmaf(-sc.z, a23.y, a23.x);
        float ns3 = o.w + fmaf(-sc.w, a23.w, a23.z);
        *reinterpret_cast<float4*>(out + q) = make_float4(ns0, ns1, ns2, ns3);
        float d0 = tg.x - ns0, d1 = tg.y - ns1, d2 = tg.z - ns2, d3 = tg.w - ns3;
        sq = fmaf(d0, d0, fmaf(d1, d1, fmaf(d2, d2, d3 * d3)));
    }

    #pragma unroll
    for (int o = 16; o > 0; o >>= 1) sq += __shfl_down_sync(0xFFFFFFFFu, sq, o);
    int lane = tid & 31, wid = tid >> 5;
    if (lane == 0) warp_sums[wid] = sq;
    __syncthreads();
    if (wid == 0) {
        float v = (lane < 8) ? warp_sums[lane] : 0.0f;
        #pragma unroll
        for (int o = 4; o > 0; o >>= 1) v += __shfl_down_sync(0xFFFFFFFFu, v, o);
        if (lane == 0) atomicAdd(&g_loss, (double)v);
    }

    if (tid == 0) {
        __threadfence();
        sh_last = (atomicAdd(&g_done, 1u) == gridDim.x - 1);
    }
    __syncthreads();
    if (sh_last && tid == 0) {
        if (write_loss) out[NE] = (float)(g_loss / (double)NE);
        g_done = 0;
    }
}

// ---------------- launcher ----------------
extern "C" void kernel_launch(void* const* d_in, const int* in_sizes, int n_in,
                              void* d_out, int out_size) {
    const int*   node_states = (const int*)  d_in[0];
    const int*   edge_states = (const int*)  d_in[1];
    const float* scalars     = (const float*)d_in[2];
    const int*   edge_index  = (const int*)  d_in[3];
    const int*   brev        = (const int*)  d_in[4];
    const float* batch_sc    = (const float*)d_in[5];
    const int*   train_step  = (const int*)  d_in[7];
    const float* node_emb    = (const float*)d_in[8];
    const float* edge_emb    = (const float*)d_in[9];
    const float* combine_W   = (const float*)d_in[10];
    const float* combine_b   = (const float*)d_in[11];
    const float* keep_W      = (const float*)d_in[12];
    const float* keep_b      = (const float*)d_in[13];
    const float* push_W      = (const float*)d_in[14];
    const float* push_b      = (const float*)d_in[15];
    const float* pushn_W     = (const float*)d_in[16];
    const float* pushn_b     = (const float*)d_in[17];
    const float* inc_W       = (const float*)d_in[18];
    const float* inc_b       = (const float*)d_in[19];

    float* out = (float*)d_out;

    int stream_blocks = (NE + 255) / 256;          // 3907
    prep_tables_kernel<<<stream_blocks + NTBLK, 256>>>(
        node_states, edge_states, scalars, combine_W, combine_b,
        node_emb, edge_emb, keep_W, keep_b, push_W, push_b,
        pushn_W, pushn_b, inc_W, inc_b, train_step);
    pass1_kernel<<<(NE + 511) / 512, 256>>>(edge_index, brev, scalars, batch_sc, out);
    pass2_kernel<<<(NN / 4 + 255) / 256, 256>>>(scalars, batch_sc, out,
                                                out_size > NE ? 1 : 0);
}

// round 9
// speedup vs baseline: 2.3502x; 1.0613x over previous
#include <cuda_runtime.h>
#include <stdint.h>

#define NN 100000
#define NE 1000000
#define HDIM 128
#define NHEADS 4
#define NTBLK 32      // table-builder blocks prefixed onto prep grid
#define EPT 4         // edges per thread (prep + pass1)

// ---------------- device scratch ----------------
__device__ float2        g_acc2[NN];        // per-dst {A,B}: acc = A - scalars[d]*B
__device__ double        g_loss;
__device__ int2          g_nrec[NN];        // {float_as_int(scalars[i]), node_code}
__device__ unsigned char g_ecodes[NE];
__device__ float         g_T[NHEADS][32];   // raw head dots: [h][0..15]=TE, [h][16..31]=TN
__device__ float4        g_P4[256];         // {p_inc, p_keep, p2+p3, p3} per (ce<<4)|cn
__device__ unsigned      g_cnt1 = 0;        // table completion counter
__device__ unsigned      g_done = 0;        // pass2 completion counter

__device__ __forceinline__ void red_add_f2(float2* addr, float a, float b) {
    asm volatile("red.global.add.v2.f32 [%0], {%1, %2};"
                 :: "l"(addr), "f"(a), "f"(b) : "memory");
}

// ---------------- kernel A: tables (blocks 0..31, shared-staged) + prep (rest) ----------------
__global__ void __launch_bounds__(256) prep_tables_kernel(
        const int*   __restrict__ node_states,
        const int*   __restrict__ edge_states,
        const float* __restrict__ scalars,
        const float* __restrict__ combine_W,   // (256,128)
        const float* __restrict__ combine_b,   // (128,)
        const float* __restrict__ node_emb,    // (16,128)
        const float* __restrict__ edge_emb,    // (16,128)
        const float* __restrict__ keep_W,  const float* __restrict__ keep_b,
        const float* __restrict__ push_W,  const float* __restrict__ push_b,
        const float* __restrict__ pushn_W, const float* __restrict__ pushn_b,
        const float* __restrict__ inc_W,   const float* __restrict__ inc_b,
        const int*   __restrict__ training_step) {
    int tid = threadIdx.x;
    int blk = blockIdx.x;

    if (blk >= NTBLK) {
        // ---------------- prep: EPT edges + EPT nodes per thread, coalesced strides ----------------
        int base = (blk - NTBLK) * 256 * EPT + tid;   // lane-coalesced, stride 256
        int4 es[EPT];
        #pragma unroll
        for (int k = 0; k < EPT; k++) {
            int e = base + k * 256;
            if (e < NE) es[k] = __ldcs(reinterpret_cast<const int4*>(edge_states) + e);
        }
        #pragma unroll
        for (int k = 0; k < EPT; k++) {
            int e = base + k * 256;
            if (e < NE)
                g_ecodes[e] = (unsigned char)(es[k].x + 2 * es[k].y + 4 * es[k].z + 8 * es[k].w);
        }
        // node prep (first 98 blocks' worth): reuse same base pattern
        #pragma unroll
        for (int k = 0; k < EPT; k++) {
            int i = base + k * 256;
            if (i < NN) {
                int4 s = reinterpret_cast<const int4*>(node_states)[i];
                g_nrec[i] = make_int2(__float_as_int(scalars[i]),
                                      s.x + 2 * s.y + 4 * s.z + 8 * s.w);
                g_acc2[i] = make_float2(0.f, 0.f);
            }
        }
        if (base == 0) g_loss = 0.0;
        return;
    }

    // ---------------- table block b: M[b][:] = emb_row_b @ W_half, then 4 head dots ----------------
    __shared__ float sW[64 * HDIM];      // 32KB staging (2 stages of 64 rows)
    __shared__ float sEmb[HDIM];
    __shared__ float sD[NHEADS][HDIM];   // per-head direction vectors
    __shared__ float sPart[256];
    __shared__ float sRed[NHEADS][4];    // per-warp partials for head dots
    __shared__ int   sh_last;

    int b = blk, k = b & 15;
    int base = (b < 16) ? 0 : HDIM;
    const float* embrow = ((b < 16) ? edge_emb : node_emb) + k * HDIM;

    if (tid < HDIM) sEmb[tid] = embrow[tid];
    {   // load 4 head direction vectors (512 elems, 2 per thread)
        const float* Wh[NHEADS] = {inc_W, keep_W, push_W, pushn_W};
        #pragma unroll
        for (int t = tid; t < NHEADS * HDIM; t += 256) {
            int h = t >> 7, i = t & 127;
            sD[h][i] = Wh[h][2 * i] - Wh[h][2 * i + 1];
        }
    }
    __syncthreads();

    int j = tid & 127, half = tid >> 7;
    float acc = 0.f;
    #pragma unroll
    for (int stage = 0; stage < 2; stage++) {
        const float4* Wv = reinterpret_cast<const float4*>(combine_W + (base + stage * 64) * HDIM);
        float4* sWv = reinterpret_cast<float4*>(sW);
        #pragma unroll
        for (int t = 0; t < 8; t++)
            sWv[t * 256 + tid] = Wv[t * 256 + tid];
        __syncthreads();
        const float* eb = sEmb + stage * 64 + half * 32;
        const float* ws = sW + (half * 32) * HDIM + j;
        #pragma unroll
        for (int i = 0; i < 32; i++)
            acc = fmaf(eb[i], ws[i * HDIM], acc);
        __syncthreads();
    }
    sPart[tid] = acc;
    __syncthreads();

    if (tid < 128) {
        float m = sPart[tid] + sPart[tid + 128];
        float v0 = m * sD[0][tid], v1 = m * sD[1][tid];
        float v2 = m * sD[2][tid], v3 = m * sD[3][tid];
        #pragma unroll
        for (int o = 16; o > 0; o >>= 1) {
            v0 += __shfl_down_sync(0xFFFFFFFFu, v0, o);
            v1 += __shfl_down_sync(0xFFFFFFFFu, v1, o);
            v2 += __shfl_down_sync(0xFFFFFFFFu, v2, o);
            v3 += __shfl_down_sync(0xFFFFFFFFu, v3, o);
        }
        int w = tid >> 5;
        if ((tid & 31) == 0) {
            sRed[0][w] = v0; sRed[1][w] = v1; sRed[2][w] = v2; sRed[3][w] = v3;
        }
    }
    __syncthreads();
    if (tid < NHEADS)
        g_T[tid][b] = sRed[tid][0] + sRed[tid][1] + sRed[tid][2] + sRed[tid][3];

    __threadfence();
    __syncthreads();
    if (tid == 0) sh_last = (atomicAdd(&g_cnt1, 1u) == NTBLK - 1u);
    __syncthreads();
    if (!sh_last) return;

    // -------- finisher: constants + bake g_P4 --------
    __shared__ float sC[NHEADS];
    __shared__ float sT[NHEADS][32];
    const float* bh[NHEADS] = {inc_b, keep_b, push_b, pushn_b};
    if (tid < 128) {
        int h = tid >> 5, l = tid & 31;
        float c = combine_b[l] * sD[h][l]
                + combine_b[l + 32] * sD[h][l + 32]
                + combine_b[l + 64] * sD[h][l + 64]
                + combine_b[l + 96] * sD[h][l + 96];
        #pragma unroll
        for (int o = 16; o > 0; o >>= 1) c += __shfl_down_sync(0xFFFFFFFFu, c, o);
        if (l == 0) sC[h] = c + bh[h][0] - bh[h][1];
    }
    if (tid < NHEADS * 32) sT[tid >> 5][tid & 31] = g_T[tid >> 5][tid & 31];
    __syncthreads();

    int step = training_step[0];
    float tau = (step == -1) ? 0.1f
              : (1.0f + (0.1f - 1.0f) * fminf((float)step / 10000.0f, 1.0f));
    float invtau = 1.0f / tau;

    {
        int ce = tid >> 4, cn = tid & 15;
        float p[NHEADS];
        #pragma unroll
        for (int h = 0; h < NHEADS; h++) {
            float logit = (sT[h][ce] + sT[h][16 + cn] + sC[h]) * invtau;
            p[h] = 1.0f / (1.0f + __expf(-logit));
        }
        g_P4[tid] = make_float4(p[0], p[1], p[2] + p[3], p[3]);
    }
    if (tid == 0) g_cnt1 = 0;   // reset for next graph replay
}

// ---------------- kernel B: main edge pass, EPT edges/thread ----------------
__global__ void __launch_bounds__(256) pass1_kernel(const int* __restrict__ edge_index,
                                                    const int* __restrict__ brev,
                                                    const float* __restrict__ scalars,
                                                    const float* __restrict__ target,
                                                    float* __restrict__ out) {
    __shared__ float4 sP4[256];
    __shared__ float warp_sums[8];
    int tid = threadIdx.x;
    sP4[tid] = g_P4[tid];
    __syncthreads();

    int base = blockIdx.x * 256 * EPT + tid;
    float sq = 0.0f;

    int  rev[EPT], src[EPT], dst[EPT];
    float s[EPT];
    bool  v[EPT];
    #pragma unroll
    for (int k = 0; k < EPT; k++) {
        int e = base + k * 256;
        v[k] = (e < NE);
        if (v[k]) {
            rev[k] = brev[e];
            s[k] = scalars[e];
            if (e < NN) { src[k] = e; dst[k] = e; }
            else { src[k] = edge_index[e]; dst[k] = edge_index[NE + e]; }
        }
    }
    unsigned ce[EPT];
    #pragma unroll
    for (int k = 0; k < EPT; k++) if (v[k]) ce[k] = g_ecodes[rev[k]];
    int2 nr[EPT];
    #pragma unroll
    for (int k = 0; k < EPT; k++) if (v[k]) nr[k] = g_nrec[src[k]];

    #pragma unroll
    for (int k = 0; k < EPT; k++) {
        if (!v[k]) continue;
        int e = base + k * 256;
        float ssrc = __int_as_float(nr[k].x);
        float4 p = sP4[(ce[k] << 4) | (unsigned)nr[k].y];
        red_add_f2(&g_acc2[dst[k]], fmaf(p.z, s[k], p.w * ssrc), p.z);
        float ns = fmaf(s[k], p.y, p.x);
        out[e] = ns;
        if (e >= NN) { float d = target[e] - ns; sq = fmaf(d, d, sq); }
    }

    #pragma unroll
    for (int o = 16; o > 0; o >>= 1) sq += __shfl_down_sync(0xFFFFFFFFu, sq, o);
    int lane = tid & 31, wid = tid >> 5;
    if (lane == 0) warp_sums[wid] = sq;
    __syncthreads();
    if (wid == 0) {
        float vv = (lane < 8) ? warp_sums[lane] : 0.0f;
        #pragma unroll
        for (int o = 4; o > 0; o >>= 1) vv += __shfl_down_sync(0xFFFFFFFFu, vv, o);
        if (lane == 0 && vv != 0.0f) atomicAdd(&g_loss, (double)vv);
    }
}

// ---------------- kernel C: finalize first N + loss (4 elems/thread) ----------------
__global__ void __launch_bounds__(256) pass2_kernel(const float* __restrict__ scalars,
                                                    const float* __restrict__ target,
                                                    float* __restrict__ out,
                                                    int write_loss) {
    __shared__ float warp_sums[8];
    __shared__ int sh_last;
    int tid = threadIdx.x;
    int q = (blockIdx.x * blockDim.x + tid) * 4;

    float sq = 0.0f;
    if (q < NN) {                                  // NN % 4 == 0
        int p = q >> 1;
        float4 a01 = reinterpret_cast<const float4*>(g_acc2)[p];
        float4 a23 = reinterpret_cast<const float4*>(g_acc2)[p + 1];
        float4 o  = *reinterpret_cast<const float4*>(out + q);
        float4 sc = *reinterpret_cast<const float4*>(scalars + q);
        float4 tg = *reinterpret_cast<const float4*>(target + q);
        float ns0 = o.x + fmaf(-sc.x, a01.y, a01.x);
        float ns1 = o.y + fmaf(-sc.y, a01.w, a01.z);
        float ns2 = o.z + fmaf(-sc.z, a23.y, a23.x);
        float ns3 = o.w + fmaf(-sc.w, a23.w, a23.z);
        *reinterpret_cast<float4*>(out + q) = make_float4(ns0, ns1, ns2, ns3);
        float d0 = tg.x - ns0, d1 = tg.y - ns1, d2 = tg.z - ns2, d3 = tg.w - ns3;
        sq = fmaf(d0, d0, fmaf(d1, d1, fmaf(d2, d2, d3 * d3)));
    }

    #pragma unroll
    for (int o = 16; o > 0; o >>= 1) sq += __shfl_down_sync(0xFFFFFFFFu, sq, o);
    int lane = tid & 31, wid = tid >> 5;
    if (lane == 0) warp_sums[wid] = sq;
    __syncthreads();
    if (wid == 0) {
        float v = (lane < 8) ? warp_sums[lane] : 0.0f;
        #pragma unroll
        for (int o = 4; o > 0; o >>= 1) v += __shfl_down_sync(0xFFFFFFFFu, v, o);
        if (lane == 0) atomicAdd(&g_loss, (double)v);
    }

    if (tid == 0) {
        __threadfence();
        sh_last = (atomicAdd(&g_done, 1u) == gridDim.x - 1);
    }
    __syncthreads();
    if (sh_last && tid == 0) {
        if (write_loss) out[NE] = (float)(g_loss / (double)NE);
        g_done = 0;
    }
}

// ---------------- launcher ----------------
extern "C" void kernel_launch(void* const* d_in, const int* in_sizes, int n_in,
                              void* d_out, int out_size) {
    const int*   node_states = (const int*)  d_in[0];
    const int*   edge_states = (const int*)  d_in[1];
    const float* scalars     = (const float*)d_in[2];
    const int*   edge_index  = (const int*)  d_in[3];
    const int*   brev        = (const int*)  d_in[4];
    const float* batch_sc    = (const float*)d_in[5];
    const int*   train_step  = (const int*)  d_in[7];
    const float* node_emb    = (const float*)d_in[8];
    const float* edge_emb    = (const float*)d_in[9];
    const float* combine_W   = (const float*)d_in[10];
    const float* combine_b   = (const float*)d_in[11];
    const float* keep_W      = (const float*)d_in[12];
    const float* keep_b      = (const float*)d_in[13];
    const float* push_W      = (const float*)d_in[14];
    const float* push_b      = (const float*)d_in[15];
    const float* pushn_W     = (const float*)d_in[16];
    const float* pushn_b     = (const float*)d_in[17];
    const float* inc_W       = (const float*)d_in[18];
    const float* inc_b       = (const float*)d_in[19];

    float* out = (float*)d_out;

    int stream_blocks = (NE + 256 * EPT - 1) / (256 * EPT);   // 977
    prep_tables_kernel<<<stream_blocks + NTBLK, 256>>>(
        node_states, edge_states, scalars, combine_W, combine_b,
        node_emb, edge_emb, keep_W, keep_b, push_W, push_b,
        pushn_W, pushn_b, inc_W, inc_b, train_step);
    pass1_kernel<<<(NE + 256 * EPT - 1) / (256 * EPT), 256>>>(
        edge_index, brev, scalars, batch_sc, out);
    pass2_kernel<<<(NN / 4 + 255) / 256, 256>>>(scalars, batch_sc, out,
                                                out_size > NE ? 1 : 0);
}